// round 1
// baseline (speedup 1.0000x reference)
#include <cuda_runtime.h>
#include <math.h>

#define NN 1024
#define BB 64
#define HH 64
#define TT 12

// ---------------- scratch (static device globals: no runtime allocation) ----------------
__device__ float g_A   [NN * NN];        // support matrix (softmax(relu(E E^T)))
__device__ float g_cat1[NN * 4224];      // [N, B*C] concat input to gcn
__device__ float g_cat2[NN * 4224];      // [N, B*C] concat input to 2nd gcn
__device__ float g_Y1  [NN * 4224];      // A @ X
__device__ float g_Y2  [NN * 4224];      // 2A@Y1 - X
__device__ float g_h   [NN * BB * HH];   // hidden state [n][b][j]
__device__ float g_r   [NN * BB * HH];   // reset gate
__device__ float g_go  [NN * BB];        // decoder GO token

// ---------------- support: A = softmax(relu(E E^T), rows) ----------------
__global__ void build_support_kernel(const float* __restrict__ emb, float* __restrict__ A) {
    __shared__ float se[NN * 8];
    __shared__ float row[NN];
    __shared__ float wred[8];
    __shared__ float red;
    int n = blockIdx.x, tid = threadIdx.x;
    for (int i = tid; i < NN * 8; i += 256) se[i] = emb[i];
    __syncthreads();
    float e[8];
    #pragma unroll
    for (int j = 0; j < 8; j++) e[j] = se[n * 8 + j];
    float mx = 0.f;
    for (int m = tid; m < NN; m += 256) {
        const float* em = &se[m * 8];
        float s = 0.f;
        #pragma unroll
        for (int j = 0; j < 8; j++) s += e[j] * em[j];
        s = fmaxf(s, 0.f);
        row[m] = s;
        mx = fmaxf(mx, s);
    }
    #pragma unroll
    for (int o = 16; o; o >>= 1) mx = fmaxf(mx, __shfl_xor_sync(0xffffffffu, mx, o));
    if ((tid & 31) == 0) wred[tid >> 5] = mx;
    __syncthreads();
    if (tid == 0) {
        float v = wred[0];
        for (int w = 1; w < 8; w++) v = fmaxf(v, wred[w]);
        red = v;
    }
    __syncthreads();
    float bmax = red;
    float sum = 0.f;
    for (int m = tid; m < NN; m += 256) {
        float v = expf(row[m] - bmax);
        row[m] = v;
        sum += v;
    }
    #pragma unroll
    for (int o = 16; o; o >>= 1) sum += __shfl_xor_sync(0xffffffffu, sum, o);
    if ((tid & 31) == 0) wred[tid >> 5] = sum;
    __syncthreads();
    if (tid == 0) {
        float v = 0.f;
        for (int w = 0; w < 8; w++) v += wred[w];
        red = v;
    }
    __syncthreads();
    float inv = 1.f / red;
    for (int m = tid; m < NN; m += 256) A[n * NN + m] = row[m] * inv;
}

// ---------------- SGEMM: Y = A[1024x1024] @ X[1024 x ldb tile]  (mode1: Y = 2*acc - Csub) ----------------
__global__ void __launch_bounds__(256) sgemm_AX(
    const float* __restrict__ A, const float* __restrict__ X,
    float* __restrict__ Y, const float* __restrict__ Csub,
    int ldb, int mode)
{
    __shared__ __align__(16) float As[16][68];
    __shared__ __align__(16) float Bs[16][64];
    int tid  = threadIdx.x;
    int row0 = blockIdx.y * 64;
    int col0 = blockIdx.x * 64;
    int ar = tid >> 2, ac4 = tid & 3;
    int bkr = tid >> 4, bcc = tid & 15;
    int ty = tid >> 4, tx = tid & 15;
    const float* Arow = A + (size_t)(row0 + ar) * NN;
    float acc[4][4];
    #pragma unroll
    for (int i = 0; i < 4; i++)
        #pragma unroll
        for (int j = 0; j < 4; j++) acc[i][j] = 0.f;

    for (int k0 = 0; k0 < NN; k0 += 16) {
        float4 av = *(const float4*)(Arow + k0 + ac4 * 4);
        float4 bv = *(const float4*)(X + (size_t)(k0 + bkr) * ldb + col0 + bcc * 4);
        __syncthreads();
        As[ac4 * 4 + 0][ar] = av.x;
        As[ac4 * 4 + 1][ar] = av.y;
        As[ac4 * 4 + 2][ar] = av.z;
        As[ac4 * 4 + 3][ar] = av.w;
        *(float4*)&Bs[bkr][bcc * 4] = bv;
        __syncthreads();
        #pragma unroll
        for (int kk = 0; kk < 16; kk++) {
            float4 a = *(const float4*)&As[kk][ty * 4];
            float4 b = *(const float4*)&Bs[kk][tx * 4];
            float aa[4] = {a.x, a.y, a.z, a.w};
            float bb[4] = {b.x, b.y, b.z, b.w};
            #pragma unroll
            for (int i = 0; i < 4; i++)
                #pragma unroll
                for (int j = 0; j < 4; j++)
                    acc[i][j] = fmaf(aa[i], bb[j], acc[i][j]);
        }
    }
    #pragma unroll
    for (int i = 0; i < 4; i++) {
        int row = row0 + ty * 4 + i;
        size_t base = (size_t)row * ldb + col0 + tx * 4;
        float4 v = make_float4(acc[i][0], acc[i][1], acc[i][2], acc[i][3]);
        if (mode == 1) {
            float4 cs = *(const float4*)(Csub + base);
            v.x = 2.f * v.x - cs.x;
            v.y = 2.f * v.y - cs.y;
            v.z = 2.f * v.z - cs.z;
            v.w = 2.f * v.w - cs.w;
        }
        *(float4*)(Y + base) = v;
    }
}

// ---------------- fused GCN weight matmul + GRU epilogue ----------------
// out[row, f] = act( bias[f] + sum_k [X|Y1|Y2](row,k) * W[k, fhalf*64 + f] )
// GATE=1: sigmoid; fhalf0 -> cat2 z*h slot, fhalf1 -> r buffer.
// GATE=0: tanh; h = r*h + (1-r)*hc (in place).
template <int C, int GATE>
__global__ void __launch_bounds__(256) fused_w_kernel(
    const float* __restrict__ F0, const float* __restrict__ F1, const float* __restrict__ F2,
    const float* __restrict__ W, const float* __restrict__ bias, int Fall,
    const float* __restrict__ h, float* __restrict__ rbuf,
    float* __restrict__ cat2, float* __restrict__ hout)
{
    constexpr int K3  = 3 * C;
    constexpr int LDF = ((K3 + 3) / 4) * 4;
    extern __shared__ float sm[];
    float* feats = sm;               // [64][LDF]
    float* Ws    = sm + 64 * LDF;    // [K3][64]
    float* bs    = Ws + K3 * 64;     // [64]
    int nblk  = blockIdx.x;          // node index (rows nblk*64 .. +63, b = r)
    int fhalf = blockIdx.y;
    int tid   = threadIdx.x;
    int base  = nblk * (64 * C);
    for (int idx = tid; idx < 64 * C; idx += 256) {
        int r = idx / C, c = idx - r * C;
        float* fd = &feats[r * LDF + c];
        fd[0]     = F0[base + idx];
        fd[C]     = F1[base + idx];
        fd[2 * C] = F2[base + idx];
    }
    for (int idx = tid; idx < K3 * 64; idx += 256) {
        int k = idx >> 6, f = idx & 63;
        Ws[idx] = W[k * Fall + fhalf * 64 + f];
    }
    if (tid < 64) bs[tid] = bias[fhalf * 64 + tid];
    __syncthreads();

    int ft = tid & 15, rt = tid >> 4;
    int f0 = ft * 4, r0 = rt * 4;
    float acc[4][4];
    #pragma unroll
    for (int i = 0; i < 4; i++)
        #pragma unroll
        for (int j = 0; j < 4; j++) acc[i][j] = bs[f0 + j];

    int k = 0;
    for (; k + 4 <= K3; k += 4) {
        float4 a4[4];
        #pragma unroll
        for (int i = 0; i < 4; i++) a4[i] = *(const float4*)&feats[(r0 + i) * LDF + k];
        #pragma unroll
        for (int kk = 0; kk < 4; kk++) {
            float4 w4 = *(const float4*)&Ws[(k + kk) * 64 + f0];
            float wj[4] = {w4.x, w4.y, w4.z, w4.w};
            #pragma unroll
            for (int i = 0; i < 4; i++) {
                float ai = ((const float*)&a4[i])[kk];
                #pragma unroll
                for (int j = 0; j < 4; j++)
                    acc[i][j] = fmaf(ai, wj[j], acc[i][j]);
            }
        }
    }
    for (; k < K3; k++) {
        float w0 = Ws[k * 64 + f0 + 0], w1 = Ws[k * 64 + f0 + 1];
        float w2 = Ws[k * 64 + f0 + 2], w3 = Ws[k * 64 + f0 + 3];
        #pragma unroll
        for (int i = 0; i < 4; i++) {
            float ai = feats[(r0 + i) * LDF + k];
            acc[i][0] = fmaf(ai, w0, acc[i][0]);
            acc[i][1] = fmaf(ai, w1, acc[i][1]);
            acc[i][2] = fmaf(ai, w2, acc[i][2]);
            acc[i][3] = fmaf(ai, w3, acc[i][3]);
        }
    }

    #pragma unroll
    for (int i = 0; i < 4; i++) {
        int row = nblk * 64 + r0 + i;
        #pragma unroll
        for (int j = 0; j < 4; j++) {
            int f = f0 + j;
            float v = acc[i][j];
            if (GATE) {
                v = 1.f / (1.f + expf(-v));
                if (fhalf == 0) {
                    // z * h_old into cat2 hidden slot
                    cat2[(size_t)row * C + (C - 64) + f] = v * h[row * 64 + f];
                } else {
                    rbuf[row * 64 + f] = v;
                }
            } else {
                float hc = tanhf(v);
                float rr = rbuf[row * 64 + f];
                float ho = h[row * 64 + f];
                hout[row * 64 + f] = rr * ho + (1.f - rr) * hc;
            }
        }
    }
}

// ---------------- concat builders ----------------
__global__ void build_cat_enc(const float* __restrict__ x, int t,
                              const float* __restrict__ h,
                              float* __restrict__ cat1, float* __restrict__ cat2) {
    const int C = 65;
    int n = blockIdx.x;
    for (int idx = threadIdx.x; idx < 64 * C; idx += 256) {
        int b = idx / C, c = idx - b * C;
        float v;
        if (c == 0) {
            v = x[(size_t)(b * TT + t) * NN + n];
            cat2[(size_t)n * 64 * C + idx] = v;
        } else {
            v = h[(n * 64 + b) * 64 + (c - 1)];
        }
        cat1[(size_t)n * 64 * C + idx] = v;
    }
}

__global__ void build_cat_dec(const float* __restrict__ yc, int t,
                              const float* __restrict__ go,
                              const float* __restrict__ h,
                              float* __restrict__ cat1, float* __restrict__ cat2) {
    const int C = 66;
    int n = blockIdx.x;
    for (int idx = threadIdx.x; idx < 64 * C; idx += 256) {
        int b = idx / C, c = idx - b * C;
        float v;
        if (c == 0)      v = go[n * 64 + b];
        else if (c == 1) v = yc[(size_t)(b * TT + t) * NN + n];
        else             v = h[(n * 64 + b) * 64 + (c - 2)];
        if (c < 2) cat2[(size_t)n * 64 * C + idx] = v;
        cat1[(size_t)n * 64 * C + idx] = v;
    }
}

// ---------------- projection: go = h @ proj_W + b, write output ----------------
__global__ void proj_kernel(const float* __restrict__ h, const float* __restrict__ pW,
                            const float* __restrict__ pb, float* __restrict__ go,
                            float* __restrict__ out, int t) {
    int row  = blockIdx.x * 8 + (threadIdx.x >> 5);
    int lane = threadIdx.x & 31;
    float s = h[row * 64 + lane] * pW[lane] + h[row * 64 + 32 + lane] * pW[32 + lane];
    #pragma unroll
    for (int o = 16; o; o >>= 1) s += __shfl_xor_sync(0xffffffffu, s, o);
    if (lane == 0) {
        float v = s + pb[0];
        go[row] = v;
        int n = row >> 6, b = row & 63;
        out[(size_t)(b * TT + t) * NN + n] = v;
    }
}

// ---------------- orchestration ----------------
extern "C" void kernel_launch(void* const* d_in, const int* in_sizes, int n_in,
                              void* d_out, int out_size) {
    const float* x    = (const float*)d_in[0];
    const float* ycov = (const float*)d_in[1];
    const float* emb  = (const float*)d_in[2];
    const float* egW  = (const float*)d_in[3];
    const float* egb  = (const float*)d_in[4];
    const float* euW  = (const float*)d_in[5];
    const float* eub  = (const float*)d_in[6];
    const float* dgW  = (const float*)d_in[7];
    const float* dgb  = (const float*)d_in[8];
    const float* duW  = (const float*)d_in[9];
    const float* dub  = (const float*)d_in[10];
    const float* pW   = (const float*)d_in[11];
    const float* pb   = (const float*)d_in[12];
    float* out = (float*)d_out;

    float *pA, *pc1, *pc2, *pY1, *pY2, *ph, *pr, *pgo;
    cudaGetSymbolAddress((void**)&pA,  g_A);
    cudaGetSymbolAddress((void**)&pc1, g_cat1);
    cudaGetSymbolAddress((void**)&pc2, g_cat2);
    cudaGetSymbolAddress((void**)&pY1, g_Y1);
    cudaGetSymbolAddress((void**)&pY2, g_Y2);
    cudaGetSymbolAddress((void**)&ph,  g_h);
    cudaGetSymbolAddress((void**)&pr,  g_r);
    cudaGetSymbolAddress((void**)&pgo, g_go);

    const int sm65 = (64 * 196 + 195 * 64 + 64) * 4;   // 100,352 B
    const int sm66 = (64 * 200 + 198 * 64 + 64) * 4;   // 102,144 B
    cudaFuncSetAttribute((const void*)fused_w_kernel<65, 1>, cudaFuncAttributeMaxDynamicSharedMemorySize, sm65);
    cudaFuncSetAttribute((const void*)fused_w_kernel<65, 0>, cudaFuncAttributeMaxDynamicSharedMemorySize, sm65);
    cudaFuncSetAttribute((const void*)fused_w_kernel<66, 1>, cudaFuncAttributeMaxDynamicSharedMemorySize, sm66);
    cudaFuncSetAttribute((const void*)fused_w_kernel<66, 0>, cudaFuncAttributeMaxDynamicSharedMemorySize, sm66);

    cudaMemsetAsync(ph,  0, (size_t)NN * 64 * 64 * sizeof(float));
    cudaMemsetAsync(pgo, 0, (size_t)NN * 64 * sizeof(float));
    build_support_kernel<<<NN, 256>>>(emb, pA);

    // ---- encoder ----
    for (int t = 0; t < TT; t++) {
        build_cat_enc<<<NN, 256>>>(x, t, ph, pc1, pc2);
        dim3 gg(65, 16);
        sgemm_AX<<<gg, 256>>>(pA, pc1, pY1, nullptr, 4160, 0);
        sgemm_AX<<<gg, 256>>>(pA, pY1, pY2, pc1,    4160, 1);
        fused_w_kernel<65, 1><<<dim3(1024, 2), 256, sm65>>>(pc1, pY1, pY2, egW, egb, 128, ph, pr, pc2, nullptr);
        sgemm_AX<<<gg, 256>>>(pA, pc2, pY1, nullptr, 4160, 0);
        sgemm_AX<<<gg, 256>>>(pA, pY1, pY2, pc2,    4160, 1);
        fused_w_kernel<65, 0><<<dim3(1024, 1), 256, sm65>>>(pc2, pY1, pY2, euW, eub, 64, ph, pr, nullptr, ph);
    }
    // ---- decoder ----
    for (int t = 0; t < TT; t++) {
        build_cat_dec<<<NN, 256>>>(ycov, t, pgo, ph, pc1, pc2);
        dim3 gg(66, 16);
        sgemm_AX<<<gg, 256>>>(pA, pc1, pY1, nullptr, 4224, 0);
        sgemm_AX<<<gg, 256>>>(pA, pY1, pY2, pc1,    4224, 1);
        fused_w_kernel<66, 1><<<dim3(1024, 2), 256, sm66>>>(pc1, pY1, pY2, dgW, dgb, 128, ph, pr, pc2, nullptr);
        sgemm_AX<<<gg, 256>>>(pA, pc2, pY1, nullptr, 4224, 0);
        sgemm_AX<<<gg, 256>>>(pA, pY1, pY2, pc2,    4224, 1);
        fused_w_kernel<66, 0><<<dim3(1024, 1), 256, sm66>>>(pc2, pY1, pY2, duW, dub, 64, ph, pr, nullptr, ph);
        proj_kernel<<<8192, 256>>>(ph, pW, pb, pgo, out, t);
    }
}

// round 2
// speedup vs baseline: 1.1586x; 1.1586x over previous
#include <cuda_runtime.h>
#include <math.h>

#define NN 1024
#define BB 64
#define HH 64
#define TT 12
#define LD 4224   // padded column count for all [N, B*C] activation buffers

// ---------------- scratch (static device globals) ----------------
__device__ float g_M   [2 * NN * NN];    // stacked [A ; A2]  (2048 x 1024)
__device__ float g_cat1[NN * LD];        // [N, B*C] concat input to gcn1
__device__ float g_cat2[NN * LD];        // [N, B*C] concat input to gcn2
__device__ float g_Y1  [NN * LD];        // A @ X
__device__ float g_Y2  [NN * LD];        // 2*A2@X - X
__device__ float g_h   [NN * BB * HH];   // hidden state [n][b][j]
__device__ float g_r   [NN * BB * HH];   // reset gate
__device__ float g_go  [NN * BB];        // decoder GO token

// ---------------- support: A = softmax(relu(E E^T), rows) ----------------
__global__ void build_support_kernel(const float* __restrict__ emb, float* __restrict__ A) {
    __shared__ float se[NN * 8];
    __shared__ float row[NN];
    __shared__ float wred[8];
    __shared__ float red;
    int n = blockIdx.x, tid = threadIdx.x;
    for (int i = tid; i < NN * 8; i += 256) se[i] = emb[i];
    __syncthreads();
    float e[8];
    #pragma unroll
    for (int j = 0; j < 8; j++) e[j] = se[n * 8 + j];
    float mx = 0.f;
    for (int m = tid; m < NN; m += 256) {
        const float* em = &se[m * 8];
        float s = 0.f;
        #pragma unroll
        for (int j = 0; j < 8; j++) s += e[j] * em[j];
        s = fmaxf(s, 0.f);
        row[m] = s;
        mx = fmaxf(mx, s);
    }
    #pragma unroll
    for (int o = 16; o; o >>= 1) mx = fmaxf(mx, __shfl_xor_sync(0xffffffffu, mx, o));
    if ((tid & 31) == 0) wred[tid >> 5] = mx;
    __syncthreads();
    if (tid == 0) {
        float v = wred[0];
        for (int w = 1; w < 8; w++) v = fmaxf(v, wred[w]);
        red = v;
    }
    __syncthreads();
    float bmax = red;
    float sum = 0.f;
    for (int m = tid; m < NN; m += 256) {
        float v = expf(row[m] - bmax);
        row[m] = v;
        sum += v;
    }
    #pragma unroll
    for (int o = 16; o; o >>= 1) sum += __shfl_xor_sync(0xffffffffu, sum, o);
    if ((tid & 31) == 0) wred[tid >> 5] = sum;
    __syncthreads();
    if (tid == 0) {
        float v = 0.f;
        for (int w = 0; w < 8; w++) v += wred[w];
        red = v;
    }
    __syncthreads();
    float inv = 1.f / red;
    for (int m = tid; m < NN; m += 256) A[n * NN + m] = row[m] * inv;
}

// ---------------- 128x128x8 double-buffered SGEMM ----------------
// MODE 0: Y1[row,col] = sum_k Amat[row,k] * X[k,col]          (plain, used for A2=A*A)
// MODE 1: Amat is 2048 rows [A;A2]. rows<1024 -> Y1 = A@X ; rows>=1024 -> Y2 = 2*A2@X - X
template<int MODE>
__global__ void __launch_bounds__(256, 2) gemm128(
    const float* __restrict__ Amat, const float* __restrict__ X, int ldb,
    float* __restrict__ Y1, float* __restrict__ Y2)
{
    __shared__ __align__(16) float As[2][8][132];
    __shared__ __align__(16) float Bs[2][8][128];
    int tid  = threadIdx.x;
    int row0 = blockIdx.y * 128;
    int col0 = blockIdx.x * 128;
    int arow = tid >> 1, acol4 = (tid & 1) << 2;
    int brow = tid >> 5, bcol4 = (tid & 31) << 2;
    int tx = tid & 15, ty = tid >> 4;

    const float* Ap = Amat + (size_t)(row0 + arow) * NN + acol4;
    const float* Xp = X + (size_t)brow * ldb + col0 + bcol4;

    float acc[8][8];
    #pragma unroll
    for (int i = 0; i < 8; i++)
        #pragma unroll
        for (int j = 0; j < 8; j++) acc[i][j] = 0.f;

    float4 av = *(const float4*)Ap;
    float4 bv = *(const float4*)Xp;
    int buf = 0;
    As[0][acol4 + 0][arow] = av.x;
    As[0][acol4 + 1][arow] = av.y;
    As[0][acol4 + 2][arow] = av.z;
    As[0][acol4 + 3][arow] = av.w;
    *(float4*)&Bs[0][brow][bcol4] = bv;
    __syncthreads();

    for (int kt = 1; kt < 128; kt++) {
        av = *(const float4*)(Ap + kt * 8);
        bv = *(const float4*)(Xp + (size_t)(kt * 8) * ldb);
        #pragma unroll
        for (int kk = 0; kk < 8; kk++) {
            float4 a0 = *(const float4*)&As[buf][kk][ty * 4];
            float4 a1 = *(const float4*)&As[buf][kk][64 + ty * 4];
            float4 b0 = *(const float4*)&Bs[buf][kk][tx * 4];
            float4 b1 = *(const float4*)&Bs[buf][kk][64 + tx * 4];
            float a[8] = {a0.x, a0.y, a0.z, a0.w, a1.x, a1.y, a1.z, a1.w};
            float b[8] = {b0.x, b0.y, b0.z, b0.w, b1.x, b1.y, b1.z, b1.w};
            #pragma unroll
            for (int i = 0; i < 8; i++)
                #pragma unroll
                for (int j = 0; j < 8; j++)
                    acc[i][j] = fmaf(a[i], b[j], acc[i][j]);
        }
        buf ^= 1;
        As[buf][acol4 + 0][arow] = av.x;
        As[buf][acol4 + 1][arow] = av.y;
        As[buf][acol4 + 2][arow] = av.z;
        As[buf][acol4 + 3][arow] = av.w;
        *(float4*)&Bs[buf][brow][bcol4] = bv;
        __syncthreads();
    }
    #pragma unroll
    for (int kk = 0; kk < 8; kk++) {
        float4 a0 = *(const float4*)&As[buf][kk][ty * 4];
        float4 a1 = *(const float4*)&As[buf][kk][64 + ty * 4];
        float4 b0 = *(const float4*)&Bs[buf][kk][tx * 4];
        float4 b1 = *(const float4*)&Bs[buf][kk][64 + tx * 4];
        float a[8] = {a0.x, a0.y, a0.z, a0.w, a1.x, a1.y, a1.z, a1.w};
        float b[8] = {b0.x, b0.y, b0.z, b0.w, b1.x, b1.y, b1.z, b1.w};
        #pragma unroll
        for (int i = 0; i < 8; i++)
            #pragma unroll
            for (int j = 0; j < 8; j++)
                acc[i][j] = fmaf(a[i], b[j], acc[i][j]);
    }

    #pragma unroll
    for (int i = 0; i < 8; i++) {
        int grow = row0 + ((i < 4) ? (ty * 4 + i) : (64 + ty * 4 + i - 4));
        int c0 = col0 + tx * 4;
        int c1 = col0 + 64 + tx * 4;
        float4 v0 = make_float4(acc[i][0], acc[i][1], acc[i][2], acc[i][3]);
        float4 v1 = make_float4(acc[i][4], acc[i][5], acc[i][6], acc[i][7]);
        if (MODE == 0 || grow < 1024) {
            float* yp = Y1 + (size_t)grow * ldb;
            *(float4*)(yp + c0) = v0;
            *(float4*)(yp + c1) = v1;
        } else {
            int r2 = grow - 1024;
            const float* xp = X + (size_t)r2 * ldb;
            float4 x0 = *(const float4*)(xp + c0);
            float4 x1 = *(const float4*)(xp + c1);
            v0.x = 2.f * v0.x - x0.x; v0.y = 2.f * v0.y - x0.y;
            v0.z = 2.f * v0.z - x0.z; v0.w = 2.f * v0.w - x0.w;
            v1.x = 2.f * v1.x - x1.x; v1.y = 2.f * v1.y - x1.y;
            v1.z = 2.f * v1.z - x1.z; v1.w = 2.f * v1.w - x1.w;
            float* yp = Y2 + (size_t)r2 * ldb;
            *(float4*)(yp + c0) = v0;
            *(float4*)(yp + c1) = v1;
        }
    }
}

// ---------------- fused gate: zr = sigmoid(GCN_W), both halves in one block ----------------
// z (cols 0..63)  -> cat2 hidden slot gets z*h_old
// r (cols 64..127)-> rbuf
template <int C>
__global__ void __launch_bounds__(256) gate_kernel(
    const float* __restrict__ F0, const float* __restrict__ F1, const float* __restrict__ F2,
    const float* __restrict__ W, const float* __restrict__ bias,
    const float* __restrict__ h, float* __restrict__ rbuf, float* __restrict__ cat2)
{
    constexpr int K3  = 3 * C;
    constexpr int LDF = ((K3 + 3) / 4) * 4;
    extern __shared__ float sm[];
    float* feats = sm;                 // [64][LDF]
    float* Ws    = sm + 64 * LDF;      // [K3][128]
    float* bs    = Ws + K3 * 128;      // [128]
    int nblk = blockIdx.x, tid = threadIdx.x;
    size_t base = (size_t)nblk * LD;
    for (int idx = tid; idx < 64 * C; idx += 256) {
        int r = idx / C, c = idx - r * C;
        float* fd = &feats[r * LDF + c];
        fd[0]     = F0[base + idx];
        fd[C]     = F1[base + idx];
        fd[2 * C] = F2[base + idx];
    }
    for (int idx = tid; idx < K3 * 128; idx += 256) Ws[idx] = W[idx];
    if (tid < 128) bs[tid] = bias[tid];
    __syncthreads();

    int ft = tid & 15, rt = tid >> 4;
    int f0 = ft * 4, r0 = rt * 4;
    float acc[4][8];
    #pragma unroll
    for (int i = 0; i < 4; i++) {
        #pragma unroll
        for (int j = 0; j < 4; j++) {
            acc[i][j]     = bs[f0 + j];
            acc[i][j + 4] = bs[64 + f0 + j];
        }
    }
    int k = 0;
    for (; k + 4 <= K3; k += 4) {
        float4 a4[4];
        #pragma unroll
        for (int i = 0; i < 4; i++) a4[i] = *(const float4*)&feats[(r0 + i) * LDF + k];
        #pragma unroll
        for (int kk = 0; kk < 4; kk++) {
            float4 wz = *(const float4*)&Ws[(k + kk) * 128 + f0];
            float4 wr = *(const float4*)&Ws[(k + kk) * 128 + 64 + f0];
            float w[8] = {wz.x, wz.y, wz.z, wz.w, wr.x, wr.y, wr.z, wr.w};
            #pragma unroll
            for (int i = 0; i < 4; i++) {
                float ai = ((const float*)&a4[i])[kk];
                #pragma unroll
                for (int j = 0; j < 8; j++) acc[i][j] = fmaf(ai, w[j], acc[i][j]);
            }
        }
    }
    for (; k < K3; k++) {
        #pragma unroll
        for (int i = 0; i < 4; i++) {
            float ai = feats[(r0 + i) * LDF + k];
            #pragma unroll
            for (int j = 0; j < 4; j++) {
                acc[i][j]     = fmaf(ai, Ws[k * 128 + f0 + j], acc[i][j]);
                acc[i][j + 4] = fmaf(ai, Ws[k * 128 + 64 + f0 + j], acc[i][j + 4]);
            }
        }
    }
    #pragma unroll
    for (int i = 0; i < 4; i++) {
        int b = r0 + i;
        int grow = nblk * 64 + b;
        #pragma unroll
        for (int j = 0; j < 4; j++) {
            int f = f0 + j;
            float z = 1.f / (1.f + expf(-acc[i][j]));
            cat2[base + b * C + (C - 64) + f] = z * h[grow * 64 + f];
            float rr = 1.f / (1.f + expf(-acc[i][j + 4]));
            rbuf[grow * 64 + f] = rr;
        }
    }
}

// ---------------- fused update: hc = tanh(GCN_W); h = r*h + (1-r)*hc ----------------
template <int C>
__global__ void __launch_bounds__(256) update_kernel(
    const float* __restrict__ F0, const float* __restrict__ F1, const float* __restrict__ F2,
    const float* __restrict__ W, const float* __restrict__ bias,
    const float* __restrict__ rbuf, float* __restrict__ h)
{
    constexpr int K3  = 3 * C;
    constexpr int LDF = ((K3 + 3) / 4) * 4;
    extern __shared__ float sm[];
    float* feats = sm;                 // [64][LDF]
    float* Ws    = sm + 64 * LDF;      // [K3][64]
    float* bs    = Ws + K3 * 64;       // [64]
    int nblk = blockIdx.x, tid = threadIdx.x;
    size_t base = (size_t)nblk * LD;
    for (int idx = tid; idx < 64 * C; idx += 256) {
        int r = idx / C, c = idx - r * C;
        float* fd = &feats[r * LDF + c];
        fd[0]     = F0[base + idx];
        fd[C]     = F1[base + idx];
        fd[2 * C] = F2[base + idx];
    }
    for (int idx = tid; idx < K3 * 64; idx += 256) Ws[idx] = W[idx];
    if (tid < 64) bs[tid] = bias[tid];
    __syncthreads();

    int ft = tid & 15, rt = tid >> 4;
    int f0 = ft * 4, r0 = rt * 4;
    float acc[4][4];
    #pragma unroll
    for (int i = 0; i < 4; i++)
        #pragma unroll
        for (int j = 0; j < 4; j++) acc[i][j] = bs[f0 + j];

    int k = 0;
    for (; k + 4 <= K3; k += 4) {
        float4 a4[4];
        #pragma unroll
        for (int i = 0; i < 4; i++) a4[i] = *(const float4*)&feats[(r0 + i) * LDF + k];
        #pragma unroll
        for (int kk = 0; kk < 4; kk++) {
            float4 w4 = *(const float4*)&Ws[(k + kk) * 64 + f0];
            float wj[4] = {w4.x, w4.y, w4.z, w4.w};
            #pragma unroll
            for (int i = 0; i < 4; i++) {
                float ai = ((const float*)&a4[i])[kk];
                #pragma unroll
                for (int j = 0; j < 4; j++) acc[i][j] = fmaf(ai, wj[j], acc[i][j]);
            }
        }
    }
    for (; k < K3; k++) {
        #pragma unroll
        for (int i = 0; i < 4; i++) {
            float ai = feats[(r0 + i) * LDF + k];
            #pragma unroll
            for (int j = 0; j < 4; j++) acc[i][j] = fmaf(ai, Ws[k * 64 + f0 + j], acc[i][j]);
        }
    }
    #pragma unroll
    for (int i = 0; i < 4; i++) {
        int grow = nblk * 64 + r0 + i;
        #pragma unroll
        for (int j = 0; j < 4; j++) {
            int f = f0 + j;
            float hc = tanhf(acc[i][j]);
            float rr = rbuf[grow * 64 + f];
            float ho = h[grow * 64 + f];
            h[grow * 64 + f] = rr * ho + (1.f - rr) * hc;
        }
    }
}

// ---------------- concat builders ----------------
__global__ void build_cat_enc(const float* __restrict__ x, int t,
                              const float* __restrict__ h,
                              float* __restrict__ cat1, float* __restrict__ cat2) {
    const int C = 65;
    int n = blockIdx.x;
    size_t base = (size_t)n * LD;
    for (int idx = threadIdx.x; idx < 64 * C; idx += 256) {
        int b = idx / C, c = idx - b * C;
        float v;
        if (c == 0) {
            v = x[(size_t)(b * TT + t) * NN + n];
            cat2[base + idx] = v;
        } else {
            v = h[(n * 64 + b) * 64 + (c - 1)];
        }
        cat1[base + idx] = v;
    }
}

__global__ void build_cat_dec(const float* __restrict__ yc, int t,
                              const float* __restrict__ go,
                              const float* __restrict__ h,
                              float* __restrict__ cat1, float* __restrict__ cat2) {
    const int C = 66;
    int n = blockIdx.x;
    size_t base = (size_t)n * LD;
    for (int idx = threadIdx.x; idx < 64 * C; idx += 256) {
        int b = idx / C, c = idx - b * C;
        float v;
        if (c == 0)      v = go[n * 64 + b];
        else if (c == 1) v = yc[(size_t)(b * TT + t) * NN + n];
        else             v = h[(n * 64 + b) * 64 + (c - 2)];
        if (c < 2) cat2[base + idx] = v;
        cat1[base + idx] = v;
    }
}

// ---------------- projection: go = h @ proj_W + b, write output ----------------
__global__ void proj_kernel(const float* __restrict__ h, const float* __restrict__ pW,
                            const float* __restrict__ pb, float* __restrict__ go,
                            float* __restrict__ out, int t) {
    int row  = blockIdx.x * 8 + (threadIdx.x >> 5);
    int lane = threadIdx.x & 31;
    float s = h[row * 64 + lane] * pW[lane] + h[row * 64 + 32 + lane] * pW[32 + lane];
    #pragma unroll
    for (int o = 16; o; o >>= 1) s += __shfl_xor_sync(0xffffffffu, s, o);
    if (lane == 0) {
        float v = s + pb[0];
        go[row] = v;
        int n = row >> 6, b = row & 63;
        out[(size_t)(b * TT + t) * NN + n] = v;
    }
}

// ---------------- orchestration ----------------
extern "C" void kernel_launch(void* const* d_in, const int* in_sizes, int n_in,
                              void* d_out, int out_size) {
    const float* x    = (const float*)d_in[0];
    const float* ycov = (const float*)d_in[1];
    const float* emb  = (const float*)d_in[2];
    const float* egW  = (const float*)d_in[3];
    const float* egb  = (const float*)d_in[4];
    const float* euW  = (const float*)d_in[5];
    const float* eub  = (const float*)d_in[6];
    const float* dgW  = (const float*)d_in[7];
    const float* dgb  = (const float*)d_in[8];
    const float* duW  = (const float*)d_in[9];
    const float* dub  = (const float*)d_in[10];
    const float* pW   = (const float*)d_in[11];
    const float* pb   = (const float*)d_in[12];
    float* out = (float*)d_out;

    float *pM, *pc1, *pc2, *pY1, *pY2, *ph, *pr, *pgo;
    cudaGetSymbolAddress((void**)&pM,  g_M);
    cudaGetSymbolAddress((void**)&pc1, g_cat1);
    cudaGetSymbolAddress((void**)&pc2, g_cat2);
    cudaGetSymbolAddress((void**)&pY1, g_Y1);
    cudaGetSymbolAddress((void**)&pY2, g_Y2);
    cudaGetSymbolAddress((void**)&ph,  g_h);
    cudaGetSymbolAddress((void**)&pr,  g_r);
    cudaGetSymbolAddress((void**)&pgo, g_go);

    // dynamic smem sizes
    const int smG65 = (64 * 196 + 195 * 128 + 128) * 4;   // 150,528 B
    const int smG66 = (64 * 200 + 198 * 128 + 128) * 4;   // 153,088 B
    const int smU65 = (64 * 196 + 195 * 64 + 64) * 4;     // 100,352 B
    const int smU66 = (64 * 200 + 198 * 64 + 64) * 4;     // 102,144 B
    cudaFuncSetAttribute((const void*)gate_kernel<65>,   cudaFuncAttributeMaxDynamicSharedMemorySize, smG65);
    cudaFuncSetAttribute((const void*)gate_kernel<66>,   cudaFuncAttributeMaxDynamicSharedMemorySize, smG66);
    cudaFuncSetAttribute((const void*)update_kernel<65>, cudaFuncAttributeMaxDynamicSharedMemorySize, smU65);
    cudaFuncSetAttribute((const void*)update_kernel<66>, cudaFuncAttributeMaxDynamicSharedMemorySize, smU66);

    cudaMemsetAsync(ph,  0, (size_t)NN * 64 * 64 * sizeof(float));
    cudaMemsetAsync(pgo, 0, (size_t)NN * 64 * sizeof(float));
    cudaMemsetAsync(pc1, 0, (size_t)NN * LD * sizeof(float));
    cudaMemsetAsync(pc2, 0, (size_t)NN * LD * sizeof(float));

    build_support_kernel<<<NN, 256>>>(emb, pM);                 // A into rows 0..1023
    gemm128<0><<<dim3(8, 8), 256>>>(pM, pM, NN, pM + (size_t)NN * NN, nullptr);  // A2 = A*A

    dim3 gg(33, 16);  // 4224 cols x 2048 rows
    // ---- encoder ----
    for (int t = 0; t < TT; t++) {
        build_cat_enc<<<NN, 256>>>(x, t, ph, pc1, pc2);
        gemm128<1><<<gg, 256>>>(pM, pc1, LD, pY1, pY2);
        gate_kernel<65><<<NN, 256, smG65>>>(pc1, pY1, pY2, egW, egb, ph, pr, pc2);
        gemm128<1><<<gg, 256>>>(pM, pc2, LD, pY1, pY2);
        update_kernel<65><<<NN, 256, smU65>>>(pc2, pY1, pY2, euW, eub, pr, ph);
    }
    // ---- decoder ----
    for (int t = 0; t < TT; t++) {
        build_cat_dec<<<NN, 256>>>(ycov, t, pgo, ph, pc1, pc2);
        gemm128<1><<<gg, 256>>>(pM, pc1, LD, pY1, pY2);
        gate_kernel<66><<<NN, 256, smG66>>>(pc1, pY1, pY2, dgW, dgb, ph, pr, pc2);
        gemm128<1><<<gg, 256>>>(pM, pc2, LD, pY1, pY2);
        update_kernel<66><<<NN, 256, smU66>>>(pc2, pY1, pY2, duW, dub, pr, ph);
        proj_kernel<<<8192, 256>>>(ph, pW, pb, pgo, out, t);
    }
}

// round 4
// speedup vs baseline: 1.9133x; 1.6514x over previous
#include <cuda_runtime.h>
#include <cuda_bf16.h>
#include <math.h>
#include <stdint.h>

#define NN 1024
#define TT 12
#define LD 4352   // 34 * 128

// ---------------- scratch ----------------
__device__ float g_M [2 * NN * NN];             // [A ; A2] fp32
__device__ __nv_bfloat16 g_Mh[2 * NN * NN];     // bf16 hi of [A ; 2*A2]
__device__ __nv_bfloat16 g_Ml[2 * NN * NN];     // bf16 lo
__device__ float g_cat1[NN * LD];
__device__ float g_cat2[NN * LD];
__device__ __nv_bfloat16 g_c1h[NN * LD];
__device__ __nv_bfloat16 g_c1l[NN * LD];
__device__ __nv_bfloat16 g_c2h[NN * LD];
__device__ __nv_bfloat16 g_c2l[NN * LD];
__device__ float g_Y1  [NN * LD];
__device__ float g_Y2  [NN * LD];
__device__ float g_h [NN * 64 * 64];
__device__ float g_r [NN * 64 * 64];
__device__ float g_go[NN * 64];

// ---------------- helpers ----------------
__device__ __forceinline__ uint32_t smem_u32(const void* p) {
    uint32_t a;
    asm("{ .reg .u64 t; cvta.to.shared.u64 t, %1; cvt.u32.u64 %0, t; }" : "=r"(a) : "l"(p));
    return a;
}
__device__ __forceinline__ void cpa16(uint32_t dst, const void* src) {
    asm volatile("cp.async.cg.shared.global [%0], [%1], 16;" :: "r"(dst), "l"(src));
}
__device__ __forceinline__ void ldsm4(uint32_t* r, uint32_t a) {
    asm volatile("ldmatrix.sync.aligned.m8n8.x4.shared.b16 {%0,%1,%2,%3}, [%4];"
        : "=r"(r[0]), "=r"(r[1]), "=r"(r[2]), "=r"(r[3]) : "r"(a));
}
__device__ __forceinline__ void ldsm4t(uint32_t* r, uint32_t a) {
    asm volatile("ldmatrix.sync.aligned.m8n8.x4.trans.shared.b16 {%0,%1,%2,%3}, [%4];"
        : "=r"(r[0]), "=r"(r[1]), "=r"(r[2]), "=r"(r[3]) : "r"(a));
}
__device__ __forceinline__ void mma_bf16(float* d, const uint32_t* a, uint32_t b0, uint32_t b1) {
    asm volatile("mma.sync.aligned.m16n8k16.row.col.f32.bf16.bf16.f32 "
        "{%0,%1,%2,%3},{%4,%5,%6,%7},{%8,%9},{%0,%1,%2,%3};"
        : "+f"(d[0]), "+f"(d[1]), "+f"(d[2]), "+f"(d[3])
        : "r"(a[0]), "r"(a[1]), "r"(a[2]), "r"(a[3]), "r"(b0), "r"(b1));
}
__device__ __forceinline__ void bsplit(float v, __nv_bfloat16& h16, __nv_bfloat16& l16) {
    h16 = __float2bfloat16(v);
    l16 = __float2bfloat16(v - __bfloat162float(h16));
}
__device__ __forceinline__ uint32_t swA(uint32_t off) { return off ^ ((off >> 3) & 0x70); }
__device__ __forceinline__ uint32_t swB(uint32_t off) { return off ^ (((off >> 8) & 7) << 4); }

// ---------------- support: A = softmax(relu(E E^T), rows) ----------------
__global__ void build_support_kernel(const float* __restrict__ emb, float* __restrict__ A) {
    __shared__ float se[NN * 8];
    __shared__ float row[NN];
    __shared__ float wred[8];
    __shared__ float red;
    int n = blockIdx.x, tid = threadIdx.x;
    for (int i = tid; i < NN * 8; i += 256) se[i] = emb[i];
    __syncthreads();
    float e[8];
    #pragma unroll
    for (int j = 0; j < 8; j++) e[j] = se[n * 8 + j];
    float mx = 0.f;
    for (int m = tid; m < NN; m += 256) {
        const float* em = &se[m * 8];
        float s = 0.f;
        #pragma unroll
        for (int j = 0; j < 8; j++) s += e[j] * em[j];
        s = fmaxf(s, 0.f);
        row[m] = s;
        mx = fmaxf(mx, s);
    }
    #pragma unroll
    for (int o = 16; o; o >>= 1) mx = fmaxf(mx, __shfl_xor_sync(0xffffffffu, mx, o));
    if ((tid & 31) == 0) wred[tid >> 5] = mx;
    __syncthreads();
    if (tid == 0) { float v = wred[0]; for (int w = 1; w < 8; w++) v = fmaxf(v, wred[w]); red = v; }
    __syncthreads();
    float bmax = red, sum = 0.f;
    for (int m = tid; m < NN; m += 256) { float v = expf(row[m] - bmax); row[m] = v; sum += v; }
    #pragma unroll
    for (int o = 16; o; o >>= 1) sum += __shfl_xor_sync(0xffffffffu, sum, o);
    if ((tid & 31) == 0) wred[tid >> 5] = sum;
    __syncthreads();
    if (tid == 0) { float v = 0.f; for (int w = 0; w < 8; w++) v += wred[w]; red = v; }
    __syncthreads();
    float inv = 1.f / red;
    for (int m = tid; m < NN; m += 256) A[n * NN + m] = row[m] * inv;
}

// ---------------- A2 = A @ A (fp32 SIMT, once per launch) ----------------
__global__ void __launch_bounds__(256, 2) gemmA2(const float* __restrict__ A, float* __restrict__ A2) {
    __shared__ __align__(16) float As[2][8][132];
    __shared__ __align__(16) float Bs[2][8][128];
    int tid = threadIdx.x;
    int row0 = blockIdx.y * 128, col0 = blockIdx.x * 128;
    int arow = tid >> 1, acol4 = (tid & 1) << 2;
    int brow = tid >> 5, bcol4 = (tid & 31) << 2;
    int tx = tid & 15, ty = tid >> 4;
    const float* Ap = A + (size_t)(row0 + arow) * NN + acol4;
    const float* Xp = A + (size_t)brow * NN + col0 + bcol4;
    float acc[8][8];
    #pragma unroll
    for (int i = 0; i < 8; i++)
        #pragma unroll
        for (int j = 0; j < 8; j++) acc[i][j] = 0.f;
    float4 av = *(const float4*)Ap;
    float4 bv = *(const float4*)Xp;
    int buf = 0;
    As[0][acol4 + 0][arow] = av.x; As[0][acol4 + 1][arow] = av.y;
    As[0][acol4 + 2][arow] = av.z; As[0][acol4 + 3][arow] = av.w;
    *(float4*)&Bs[0][brow][bcol4] = bv;
    __syncthreads();
    for (int kt = 1; kt < 128; kt++) {
        av = *(const float4*)(Ap + kt * 8);
        bv = *(const float4*)(Xp + (size_t)(kt * 8) * NN);
        #pragma unroll
        for (int kk = 0; kk < 8; kk++) {
            float4 a0 = *(const float4*)&As[buf][kk][ty * 4];
            float4 a1 = *(const float4*)&As[buf][kk][64 + ty * 4];
            float4 b0 = *(const float4*)&Bs[buf][kk][tx * 4];
            float4 b1 = *(const float4*)&Bs[buf][kk][64 + tx * 4];
            float a[8] = {a0.x,a0.y,a0.z,a0.w,a1.x,a1.y,a1.z,a1.w};
            float b[8] = {b0.x,b0.y,b0.z,b0.w,b1.x,b1.y,b1.z,b1.w};
            #pragma unroll
            for (int i = 0; i < 8; i++)
                #pragma unroll
                for (int j = 0; j < 8; j++) acc[i][j] = fmaf(a[i], b[j], acc[i][j]);
        }
        buf ^= 1;
        As[buf][acol4 + 0][arow] = av.x; As[buf][acol4 + 1][arow] = av.y;
        As[buf][acol4 + 2][arow] = av.z; As[buf][acol4 + 3][arow] = av.w;
        *(float4*)&Bs[buf][brow][bcol4] = bv;
        __syncthreads();
    }
    #pragma unroll
    for (int kk = 0; kk < 8; kk++) {
        float4 a0 = *(const float4*)&As[buf][kk][ty * 4];
        float4 a1 = *(const float4*)&As[buf][kk][64 + ty * 4];
        float4 b0 = *(const float4*)&Bs[buf][kk][tx * 4];
        float4 b1 = *(const float4*)&Bs[buf][kk][64 + tx * 4];
        float a[8] = {a0.x,a0.y,a0.z,a0.w,a1.x,a1.y,a1.z,a1.w};
        float b[8] = {b0.x,b0.y,b0.z,b0.w,b1.x,b1.y,b1.z,b1.w};
        #pragma unroll
        for (int i = 0; i < 8; i++)
            #pragma unroll
            for (int j = 0; j < 8; j++) acc[i][j] = fmaf(a[i], b[j], acc[i][j]);
    }
    #pragma unroll
    for (int i = 0; i < 8; i++) {
        int grow = row0 + ((i < 4) ? (ty * 4 + i) : (64 + ty * 4 + i - 4));
        float* yp = A2 + (size_t)grow * NN;
        *(float4*)(yp + col0 + tx * 4)       = make_float4(acc[i][0], acc[i][1], acc[i][2], acc[i][3]);
        *(float4*)(yp + col0 + 64 + tx * 4)  = make_float4(acc[i][4], acc[i][5], acc[i][6], acc[i][7]);
    }
}

// ---------------- M -> bf16 hi/lo (fold 2x into bottom half) ----------------
__global__ void convert_M(const float* __restrict__ M,
                          __nv_bfloat16* __restrict__ Mh, __nv_bfloat16* __restrict__ Ml) {
    int i = blockIdx.x * 256 + threadIdx.x;
    float v = M[i];
    if (i >= NN * NN) v *= 2.f;
    __nv_bfloat16 h, l;
    bsplit(v, h, l);
    Mh[i] = h;
    Ml[i] = l;
}

// ---------------- HMMA split-bf16 diffusion GEMM ----------------
// grid (34, 16): col0 = bx*128, row0 = by*128 over [A ; 2*A2] (2048 rows)
// by<8:  Y1 = A @ X       by>=8: Y2 = (2*A2) @ X - X
// smem per stage: Ah 16K | Al 16K | Bh 16K | Bl 16K  (KC=64)
#define KC 64
#define STG 65536
__global__ void __launch_bounds__(256, 1) hmma_gemm(
    const __nv_bfloat16* __restrict__ Mh, const __nv_bfloat16* __restrict__ Ml,
    const __nv_bfloat16* __restrict__ Xh, const __nv_bfloat16* __restrict__ Xl,
    const float* __restrict__ Xf, float* __restrict__ Y1, float* __restrict__ Y2)
{
    extern __shared__ __align__(1024) char smem[];
    uint32_t sb = smem_u32(smem);
    int tid = threadIdx.x;
    int lane = tid & 31, wid = tid >> 5;
    int wm = wid >> 1, wn = wid & 1;
    int row0 = blockIdx.y * 128;
    int col0 = blockIdx.x * 128;

    float acc[2][8][4];
    #pragma unroll
    for (int mt = 0; mt < 2; mt++)
        #pragma unroll
        for (int nt = 0; nt < 8; nt++)
            #pragma unroll
            for (int j = 0; j < 4; j++) acc[mt][nt][j] = 0.f;

    auto load_stage = [&](int it) {
        uint32_t base = sb + (it & 1) * STG;
        int k0 = it * KC;
        #pragma unroll
        for (int i = tid; i < 1024; i += 256) {
            int r = i >> 3, c = i & 7;
            uint32_t sw = swA((uint32_t)(r * 128 + c * 16));
            size_t g = (size_t)(row0 + r) * NN + k0 + c * 8;
            cpa16(base + sw, Mh + g);
            cpa16(base + 16384 + sw, Ml + g);
        }
        #pragma unroll
        for (int i = tid; i < 1024; i += 256) {
            int k = i >> 4, c = i & 15;
            uint32_t sw = swB((uint32_t)(k * 256 + c * 16));
            size_t g = (size_t)(k0 + k) * LD + col0 + c * 8;
            cpa16(base + 32768 + sw, Xh + g);
            cpa16(base + 49152 + sw, Xl + g);
        }
        asm volatile("cp.async.commit_group;" ::: "memory");
    };

    load_stage(0);
    load_stage(1);

    // precomputed intra-tile fragment offsets
    int a_r = wm * 32 + (lane & 15);
    int a_ch = (lane >> 4);
    int b_k = (lane & 7) + ((lane >> 3) & 1) * 8;
    int b_n8 = ((lane >> 4) & 1) * 8;

    #pragma unroll 1
    for (int it = 0; it < 16; it++) {
        if (it < 15) asm volatile("cp.async.wait_group 1;" ::: "memory");
        else         asm volatile("cp.async.wait_group 0;" ::: "memory");
        __syncthreads();
        uint32_t base = sb + (it & 1) * STG;
        #pragma unroll
        for (int kk = 0; kk < 4; kk++) {
            uint32_t aH[2][4], aL[2][4];
            #pragma unroll
            for (int mt = 0; mt < 2; mt++) {
                uint32_t off = swA((uint32_t)((a_r + mt * 16) * 128 + (kk * 2 + a_ch) * 16));
                ldsm4(aH[mt], base + off);
                ldsm4(aL[mt], base + 16384 + off);
            }
            uint32_t bH[4][4], bL[4][4];
            #pragma unroll
            for (int p = 0; p < 4; p++) {
                int nb = wn * 64 + p * 16 + b_n8;
                uint32_t off = swB((uint32_t)((kk * 16 + b_k) * 256 + nb * 2));
                ldsm4t(bH[p], base + 32768 + off);
                ldsm4t(bL[p], base + 49152 + off);
            }
            #pragma unroll
            for (int mt = 0; mt < 2; mt++) {
                #pragma unroll
                for (int p = 0; p < 4; p++) {
                    mma_bf16(acc[mt][2 * p],     aH[mt], bH[p][0], bH[p][1]);
                    mma_bf16(acc[mt][2 * p],     aH[mt], bL[p][0], bL[p][1]);
                    mma_bf16(acc[mt][2 * p],     aL[mt], bH[p][0], bH[p][1]);
                    mma_bf16(acc[mt][2 * p + 1], aH[mt], bH[p][2], bH[p][3]);
                    mma_bf16(acc[mt][2 * p + 1], aH[mt], bL[p][2], bL[p][3]);
                    mma_bf16(acc[mt][2 * p + 1], aL[mt], bH[p][2], bH[p][3]);
                }
            }
        }
        __syncthreads();
        if (it + 2 < 16) load_stage(it + 2);
    }

    // epilogue
    int r_lo = lane >> 2;
    int c_lo = (lane & 3) * 2;
    if (row0 < 1024) {
        #pragma unroll
        for (int mt = 0; mt < 2; mt++) {
            int r = row0 + wm * 32 + mt * 16 + r_lo;
            #pragma unroll
            for (int nt = 0; nt < 8; nt++) {
                int c = col0 + wn * 64 + nt * 8 + c_lo;
                *(float2*)(Y1 + (size_t)r * LD + c)       = make_float2(acc[mt][nt][0], acc[mt][nt][1]);
                *(float2*)(Y1 + (size_t)(r + 8) * LD + c) = make_float2(acc[mt][nt][2], acc[mt][nt][3]);
            }
        }
    } else {
        #pragma unroll
        for (int mt = 0; mt < 2; mt++) {
            int r = row0 - 1024 + wm * 32 + mt * 16 + r_lo;
            #pragma unroll
            for (int nt = 0; nt < 8; nt++) {
                int c = col0 + wn * 64 + nt * 8 + c_lo;
                float2 x0 = *(const float2*)(Xf + (size_t)r * LD + c);
                float2 x1 = *(const float2*)(Xf + (size_t)(r + 8) * LD + c);
                *(float2*)(Y2 + (size_t)r * LD + c)       = make_float2(acc[mt][nt][0] - x0.x, acc[mt][nt][1] - x0.y);
                *(float2*)(Y2 + (size_t)(r + 8) * LD + c) = make_float2(acc[mt][nt][2] - x1.x, acc[mt][nt][3] - x1.y);
            }
        }
    }
}

// ---------------- fused gate ----------------
template <int C>
__global__ void __launch_bounds__(256) gate_kernel(
    const float* __restrict__ F0, const float* __restrict__ F1, const float* __restrict__ F2,
    const float* __restrict__ W, const float* __restrict__ bias,
    const float* __restrict__ h, float* __restrict__ rbuf,
    float* __restrict__ cat2, __nv_bfloat16* __restrict__ c2h, __nv_bfloat16* __restrict__ c2l)
{
    constexpr int K3  = 3 * C;
    constexpr int LDF = ((K3 + 3) / 4) * 4;
    extern __shared__ float sm[];
    float* feats = sm;
    float* Ws    = sm + 64 * LDF;
    float* bs    = Ws + K3 * 128;
    int nblk = blockIdx.x, tid = threadIdx.x;
    size_t base = (size_t)nblk * LD;
    for (int idx = tid; idx < 64 * C; idx += 256) {
        int r = idx / C, c = idx - r * C;
        float* fd = &feats[r * LDF + c];
        fd[0]     = F0[base + idx];
        fd[C]     = F1[base + idx];
        fd[2 * C] = F2[base + idx];
    }
    for (int idx = tid; idx < K3 * 128; idx += 256) Ws[idx] = W[idx];
    if (tid < 128) bs[tid] = bias[tid];
    __syncthreads();

    int ft = tid & 15, rt = tid >> 4;
    int f0 = ft * 4, r0 = rt * 4;
    float acc[4][8];
    #pragma unroll
    for (int i = 0; i < 4; i++)
        #pragma unroll
        for (int j = 0; j < 4; j++) { acc[i][j] = bs[f0 + j]; acc[i][j + 4] = bs[64 + f0 + j]; }
    int k = 0;
    for (; k + 4 <= K3; k += 4) {
        float4 a4[4];
        #pragma unroll
        for (int i = 0; i < 4; i++) a4[i] = *(const float4*)&feats[(r0 + i) * LDF + k];
        #pragma unroll
        for (int kk = 0; kk < 4; kk++) {
            float4 wz = *(const float4*)&Ws[(k + kk) * 128 + f0];
            float4 wr = *(const float4*)&Ws[(k + kk) * 128 + 64 + f0];
            float wv[8] = {wz.x,wz.y,wz.z,wz.w,wr.x,wr.y,wr.z,wr.w};
            #pragma unroll
            for (int i = 0; i < 4; i++) {
                float ai = ((const float*)&a4[i])[kk];
                #pragma unroll
                for (int j = 0; j < 8; j++) acc[i][j] = fmaf(ai, wv[j], acc[i][j]);
            }
        }
    }
    for (; k < K3; k++) {
        #pragma unroll
        for (int i = 0; i < 4; i++) {
            float ai = feats[(r0 + i) * LDF + k];
            #pragma unroll
            for (int j = 0; j < 4; j++) {
                acc[i][j]     = fmaf(ai, Ws[k * 128 + f0 + j], acc[i][j]);
                acc[i][j + 4] = fmaf(ai, Ws[k * 128 + 64 + f0 + j], acc[i][j + 4]);
            }
        }
    }
    #pragma unroll
    for (int i = 0; i < 4; i++) {
        int b = r0 + i;
        int grow = nblk * 64 + b;
        #pragma unroll
        for (int j = 0; j < 4; j++) {
            int f = f0 + j;
            float z = 1.f / (1.f + expf(-acc[i][j]));
            float v = z * h[grow * 64 + f];
            size_t pos = base + b * C + (C - 64) + f;
            cat2[pos] = v;
            __nv_bfloat16 hh, ll;
            bsplit(v, hh, ll);
            c2h[pos] = hh;
            c2l[pos] = ll;
            float rr = 1.f / (1.f + expf(-acc[i][j + 4]));
            rbuf[grow * 64 + f] = rr;
        }
    }
}

// ---------------- fused update ----------------
template <int C>
__global__ void __launch_bounds__(256) update_kernel(
    const float* __restrict__ F0, const float* __restrict__ F1, const float* __restrict__ F2,
    const float* __restrict__ W, const float* __restrict__ bias,
    const float* __restrict__ rbuf, float* __restrict__ h)
{
    constexpr int K3  = 3 * C;
    constexpr int LDF = ((K3 + 3) / 4) * 4;
    extern __shared__ float sm[];
    float* feats = sm;
    float* Ws    = sm + 64 * LDF;
    float* bs    = Ws + K3 * 64;
    int nblk = blockIdx.x, tid = threadIdx.x;
    size_t base = (size_t)nblk * LD;
    for (int idx = tid; idx < 64 * C; idx += 256) {
        int r = idx / C, c = idx - r * C;
        float* fd = &feats[r * LDF + c];
        fd[0]     = F0[base + idx];
        fd[C]     = F1[base + idx];
        fd[2 * C] = F2[base + idx];
    }
    for (int idx = tid; idx < K3 * 64; idx += 256) Ws[idx] = W[idx];
    if (tid < 64) bs[tid] = bias[tid];
    __syncthreads();

    int ft = tid & 15, rt = tid >> 4;
    int f0 = ft * 4, r0 = rt * 4;
    float acc[4][4];
    #pragma unroll
    for (int i = 0; i < 4; i++)
        #pragma unroll
        for (int j = 0; j < 4; j++) acc[i][j] = bs[f0 + j];
    int k = 0;
    for (; k + 4 <= K3; k += 4) {
        float4 a4[4];
        #pragma unroll
        for (int i = 0; i < 4; i++) a4[i] = *(const float4*)&feats[(r0 + i) * LDF + k];
        #pragma unroll
        for (int kk = 0; kk < 4; kk++) {
            float4 w4 = *(const float4*)&Ws[(k + kk) * 64 + f0];
            float wj[4] = {w4.x, w4.y, w4.z, w4.w};
            #pragma unroll
            for (int i = 0; i < 4; i++) {
                float ai = ((const float*)&a4[i])[kk];
                #pragma unroll
                for (int j = 0; j < 4; j++) acc[i][j] = fmaf(ai, wj[j], acc[i][j]);
            }
        }
    }
    for (; k < K3; k++) {
        #pragma unroll
        for (int i = 0; i < 4; i++) {
            float ai = feats[(r0 + i) * LDF + k];
            #pragma unroll
            for (int j = 0; j < 4; j++) acc[i][j] = fmaf(ai, Ws[k * 64 + f0 + j], acc[i][j]);
        }
    }
    #pragma unroll
    for (int i = 0; i < 4; i++) {
        int grow = nblk * 64 + r0 + i;
        #pragma unroll
        for (int j = 0; j < 4; j++) {
            int f = f0 + j;
            float hc = tanhf(acc[i][j]);
            float rr = rbuf[grow * 64 + f];
            float ho = h[grow * 64 + f];
            h[grow * 64 + f] = rr * ho + (1.f - rr) * hc;
        }
    }
}

// ---------------- concat builders (fp32 + bf16 hi/lo) ----------------
__global__ void build_cat_enc(const float* __restrict__ x, int t,
                              const float* __restrict__ h,
                              float* __restrict__ cat1,
                              __nv_bfloat16* __restrict__ c1h, __nv_bfloat16* __restrict__ c1l,
                              float* __restrict__ cat2,
                              __nv_bfloat16* __restrict__ c2h, __nv_bfloat16* __restrict__ c2l) {
    const int C = 65;
    int n = blockIdx.x;
    size_t base = (size_t)n * LD;
    for (int idx = threadIdx.x; idx < 64 * C; idx += 256) {
        int b = idx / C, c = idx - b * C;
        float v;
        __nv_bfloat16 hh, ll;
        if (c == 0) {
            v = x[(size_t)(b * TT + t) * NN + n];
            bsplit(v, hh, ll);
            cat2[base + idx] = v;
            c2h[base + idx] = hh;
            c2l[base + idx] = ll;
        } else {
            v = h[(n * 64 + b) * 64 + (c - 1)];
            bsplit(v, hh, ll);
        }
        cat1[base + idx] = v;
        c1h[base + idx] = hh;
        c1l[base + idx] = ll;
    }
}
__global__ void build_cat_dec(const float* __restrict__ yc, int t,
                              const float* __restrict__ go,
                              const float* __restrict__ h,
                              float* __restrict__ cat1,
                              __nv_bfloat16* __restrict__ c1h, __nv_bfloat16* __restrict__ c1l,
                              float* __restrict__ cat2,
                              __nv_bfloat16* __restrict__ c2h, __nv_bfloat16* __restrict__ c2l) {
    const int C = 66;
    int n = blockIdx.x;
    size_t base = (size_t)n * LD;
    for (int idx = threadIdx.x; idx < 64 * C; idx += 256) {
        int b = idx / C, c = idx - b * C;
        float v;
        if (c == 0)      v = go[n * 64 + b];
        else if (c == 1) v = yc[(size_t)(b * TT + t) * NN + n];
        else             v = h[(n * 64 + b) * 64 + (c - 2)];
        __nv_bfloat16 hh, ll;
        bsplit(v, hh, ll);
        if (c < 2) {
            cat2[base + idx] = v;
            c2h[base + idx] = hh;
            c2l[base + idx] = ll;
        }
        cat1[base + idx] = v;
        c1h[base + idx] = hh;
        c1l[base + idx] = ll;
    }
}

// ---------------- projection ----------------
__global__ void proj_kernel(const float* __restrict__ h, const float* __restrict__ pW,
                            const float* __restrict__ pb, float* __restrict__ go,
                            float* __restrict__ out, int t) {
    int row  = blockIdx.x * 8 + (threadIdx.x >> 5);
    int lane = threadIdx.x & 31;
    float s = h[row * 64 + lane] * pW[lane] + h[row * 64 + 32 + lane] * pW[32 + lane];
    #pragma unroll
    for (int o = 16; o; o >>= 1) s += __shfl_xor_sync(0xffffffffu, s, o);
    if (lane == 0) {
        float v = s + pb[0];
        go[row] = v;
        int n = row >> 6, b = row & 63;
        out[(size_t)(b * TT + t) * NN + n] = v;
    }
}

// ---------------- orchestration ----------------
extern "C" void kernel_launch(void* const* d_in, const int* in_sizes, int n_in,
                              void* d_out, int out_size) {
    const float* x    = (const float*)d_in[0];
    const float* ycov = (const float*)d_in[1];
    const float* emb  = (const float*)d_in[2];
    const float* egW  = (const float*)d_in[3];
    const float* egb  = (const float*)d_in[4];
    const float* euW  = (const float*)d_in[5];
    const float* eub  = (const float*)d_in[6];
    const float* dgW  = (const float*)d_in[7];
    const float* dgb  = (const float*)d_in[8];
    const float* duW  = (const float*)d_in[9];
    const float* dub  = (const float*)d_in[10];
    const float* pW   = (const float*)d_in[11];
    const float* pb   = (const float*)d_in[12];
    float* out = (float*)d_out;

    float *pM, *pc1, *pc2, *pY1, *pY2, *ph, *pr, *pgo;
    __nv_bfloat16 *pMh, *pMl, *p1h, *p1l, *p2h, *p2l;
    cudaGetSymbolAddress((void**)&pM,  g_M);
    cudaGetSymbolAddress((void**)&pMh, g_Mh);
    cudaGetSymbolAddress((void**)&pMl, g_Ml);
    cudaGetSymbolAddress((void**)&pc1, g_cat1);
    cudaGetSymbolAddress((void**)&pc2, g_cat2);
    cudaGetSymbolAddress((void**)&p1h, g_c1h);
    cudaGetSymbolAddress((void**)&p1l, g_c1l);
    cudaGetSymbolAddress((void**)&p2h, g_c2h);
    cudaGetSymbolAddress((void**)&p2l, g_c2l);
    cudaGetSymbolAddress((void**)&pY1, g_Y1);
    cudaGetSymbolAddress((void**)&pY2, g_Y2);
    cudaGetSymbolAddress((void**)&ph,  g_h);
    cudaGetSymbolAddress((void**)&pr,  g_r);
    cudaGetSymbolAddress((void**)&pgo, g_go);

    const int smG65 = (64 * 196 + 195 * 128 + 128) * 4;
    const int smG66 = (64 * 200 + 198 * 128 + 128) * 4;
    const int smU65 = (64 * 196 + 195 * 64 + 64) * 4;
    const int smU66 = (64 * 200 + 198 * 64 + 64) * 4;
    const int smHM  = 2 * STG;   // 131072
    cudaFuncSetAttribute((const void*)gate_kernel<65>,   cudaFuncAttributeMaxDynamicSharedMemorySize, smG65);
    cudaFuncSetAttribute((const void*)gate_kernel<66>,   cudaFuncAttributeMaxDynamicSharedMemorySize, smG66);
    cudaFuncSetAttribute((const void*)update_kernel<65>, cudaFuncAttributeMaxDynamicSharedMemorySize, smU65);
    cudaFuncSetAttribute((const void*)update_kernel<66>, cudaFuncAttributeMaxDynamicSharedMemorySize, smU66);
    cudaFuncSetAttribute((const void*)hmma_gemm,         cudaFuncAttributeMaxDynamicSharedMemorySize, smHM);

    cudaMemsetAsync(ph,  0, (size_t)NN * 64 * 64 * sizeof(float));
    cudaMemsetAsync(pgo, 0, (size_t)NN * 64 * sizeof(float));
    cudaMemsetAsync(pc1, 0, (size_t)NN * LD * sizeof(float));
    cudaMemsetAsync(pc2, 0, (size_t)NN * LD * sizeof(float));
    cudaMemsetAsync(p1h, 0, (size_t)NN * LD * sizeof(__nv_bfloat16));
    cudaMemsetAsync(p1l, 0, (size_t)NN * LD * sizeof(__nv_bfloat16));
    cudaMemsetAsync(p2h, 0, (size_t)NN * LD * sizeof(__nv_bfloat16));
    cudaMemsetAsync(p2l, 0, (size_t)NN * LD * sizeof(__nv_bfloat16));

    build_support_kernel<<<NN, 256>>>(emb, pM);
    gemmA2<<<dim3(8, 8), 256>>>(pM, pM + (size_t)NN * NN);
    convert_M<<<2 * NN * NN / 256, 256>>>(pM, pMh, pMl);

    dim3 gg(LD / 128, 16);
    for (int t = 0; t < TT; t++) {
        build_cat_enc<<<NN, 256>>>(x, t, ph, pc1, p1h, p1l, pc2, p2h, p2l);
        hmma_gemm<<<gg, 256, smHM>>>(pMh, pMl, p1h, p1l, pc1, pY1, pY2);
        gate_kernel<65><<<NN, 256, smG65>>>(pc1, pY1, pY2, egW, egb, ph, pr, pc2, p2h, p2l);
        hmma_gemm<<<gg, 256, smHM>>>(pMh, pMl, p2h, p2l, pc2, pY1, pY2);
        update_kernel<65><<<NN, 256, smU65>>>(pc2, pY1, pY2, euW, eub, pr, ph);
    }
    for (int t = 0; t < TT; t++) {
        build_cat_dec<<<NN, 256>>>(ycov, t, pgo, ph, pc1, p1h, p1l, pc2, p2h, p2l);
        hmma_gemm<<<gg, 256, smHM>>>(pMh, pMl, p1h, p1l, pc1, pY1, pY2);
        gate_kernel<66><<<NN, 256, smG66>>>(pc1, pY1, pY2, dgW, dgb, ph, pr, pc2, p2h, p2l);
        hmma_gemm<<<gg, 256, smHM>>>(pMh, pMl, p2h, p2l, pc2, pY1, pY2);
        update_kernel<66><<<NN, 256, smU66>>>(pc2, pY1, pY2, duW, dub, pr, ph);
        proj_kernel<<<8192, 256>>>(ph, pW, pb, pgo, out, t);
    }
}